// round 12
// baseline (speedup 1.0000x reference)
#include <cuda_runtime.h>
#include <cuda_fp16.h>
#include <cstdint>

#define S 2048
#define H 1024
#define E 8
#define INTER 2048
#define TWO_I 4096
#define ALPHA 1.702f
#define LIMIT 7.0f
#define NPERS 456   // 152 SMs * 3 CTAs

// ---------------- device scratch (device-code references ONLY) ----------------
__device__ int   g_cnt[E];
__device__ int   g_tok[E * S];
__device__ float g_wt[E * S];
__device__ int   g_moff[E + 1];   // prefix of ceil(cnt/128)
__device__ int   g_q0, g_q1;      // work queues
__device__ __align__(128) __half g_xh[S * H];
__device__ __align__(128) __half g_guh[(size_t)E * TWO_I * H];
__device__ __align__(128) __half g_dwh[(size_t)E * H * INTER];
__device__ __align__(128) __half g_ah[(size_t)E * S * INTER];

// down-weight transpose tiles: 64(R) x 32(C) over [E][INTER][H]
#define NTR (E * (INTER / 64) * (H / 32))   // 8192

// ---------------- helpers ----------------
__device__ __forceinline__ uint32_t s2u(const void* p) {
    uint32_t a;
    asm("{ .reg .u64 t; cvta.to.shared.u64 t, %1; cvt.u32.u64 %0, t; }" : "=r"(a) : "l"(p));
    return a;
}
__device__ __forceinline__ uint32_t swz128(uint32_t o) { return o ^ ((o >> 3) & 0x70); }

#define CP16(dst, src) \
    asm volatile("cp.async.cg.shared.global [%0], [%1], 16;" :: "r"(dst), "l"(src) : "memory")
#define CP_COMMIT() asm volatile("cp.async.commit_group;" ::: "memory")
#define CP_WAIT0()  asm volatile("cp.async.wait_group 0;" ::: "memory")
#define CP_WAIT1()  asm volatile("cp.async.wait_group 1;" ::: "memory")

__device__ __forceinline__ void ldsm4(uint32_t addr, uint32_t* r) {
    asm volatile("ldmatrix.sync.aligned.m8n8.x4.shared.b16 {%0,%1,%2,%3}, [%4];"
                 : "=r"(r[0]), "=r"(r[1]), "=r"(r[2]), "=r"(r[3]) : "r"(addr));
}
__device__ __forceinline__ void mma16816(float* d, const uint32_t* a, uint32_t b0, uint32_t b1) {
    asm volatile(
        "mma.sync.aligned.m16n8k16.row.col.f32.f16.f16.f32 "
        "{%0,%1,%2,%3}, {%4,%5,%6,%7}, {%8,%9}, {%0,%1,%2,%3};"
        : "+f"(d[0]), "+f"(d[1]), "+f"(d[2]), "+f"(d[3])
        : "r"(a[0]), "r"(a[1]), "r"(a[2]), "r"(a[3]), "r"(b0), "r"(b1));
}

// Stage: Ah 16K | Bh 8K = 24KB; 3 stages -> 3 CTAs/SM
#define BOFF_H 16384
#define STAGE  24576
#define SMEM_REQ (1024 + 3 * STAGE)

// one K=64 chunk; block tile 128x64, warp tile 64x32 (4 warps)
__device__ __forceinline__ void compute_chunk(uint32_t base, int wm, int wn, int lane,
                                              float acc[4][4][4])
{
    uint32_t sA = base, sB = base + BOFF_H;
    int arow = wm + (lane & 15);
    int brow = wn + (lane & 15);
    uint32_t klane = (uint32_t)((lane >> 4) << 4);
#pragma unroll
    for (int ks = 0; ks < 4; ks++) {
        uint32_t ko = (uint32_t)(ks * 32) + klane;
        uint32_t ah[4][4];
#pragma unroll
        for (int mf = 0; mf < 4; mf++) {
            uint32_t off = swz128((uint32_t)((arow + mf * 16) * 128) + ko);
            ldsm4(sA + off, ah[mf]);
        }
#pragma unroll
        for (int nh = 0; nh < 2; nh++) {
            uint32_t boff = swz128((uint32_t)((brow + nh * 16) * 128) + ko);
            uint32_t bh[4];
            ldsm4(sB + boff, bh);
#pragma unroll
            for (int mf = 0; mf < 4; mf++) {
                mma16816(acc[mf][2 * nh],     ah[mf], bh[0], bh[2]);
                mma16816(acc[mf][2 * nh + 1], ah[mf], bh[1], bh[3]);
            }
        }
    }
}

__device__ __forceinline__ void issue_chunk(
    uint32_t base, int k0,
    const __half* Ah, const __half* Bh,
    const size_t* asrc, const size_t* bsrc,
    const uint32_t* adst, const uint32_t* bdst)
{
#pragma unroll
    for (int i = 0; i < 8; i++)
        CP16(base + adst[i], (const char*)(Ah + asrc[i] + k0));
#pragma unroll
    for (int i = 0; i < 4; i++)
        CP16(base + BOFF_H + bdst[i], (const char*)(Bh + bsrc[i] + k0));
    CP_COMMIT();
}

// map tile-group index q -> expert via prefix sums
__device__ __forceinline__ int find_expert(int q) {
    int e = 0;
#pragma unroll
    for (int i = 0; i < E - 1; i++)
        if (q >= g_moff[i + 1]) e = i + 1;
    return e;
}

// ---------------------------------------------------------------------------
__global__ void init_kernel() {
    if (threadIdx.x < E) g_cnt[threadIdx.x] = 0;
    if (threadIdx.x == 0) { g_q0 = 0; g_q1 = 0; }
}

__global__ void prefix_kernel() {
    if (threadIdx.x == 0) {
        int acc = 0;
#pragma unroll
        for (int e = 0; e < E; e++) {
            g_moff[e] = acc;
            acc += (g_cnt[e] + 127) >> 7;
        }
        g_moff[E] = acc;
    }
}

// ---------------------------------------------------------------------------
// Router: one warp per token, shuffle reduce.
// ---------------------------------------------------------------------------
__global__ __launch_bounds__(256) void router_kernel(
    const float* __restrict__ x, const float* __restrict__ rw, const float* __restrict__ rb)
{
    int warp = threadIdx.x >> 5, lane = threadIdx.x & 31;
    int t = blockIdx.x * 8 + warp;
    const float* xr = x + (size_t)t * H;

    float acc[E];
#pragma unroll
    for (int e = 0; e < E; e++) acc[e] = 0.0f;
#pragma unroll 4
    for (int i = 0; i < 32; i++) {
        int h = i * 32 + lane;
        float xv = xr[h];
        const float4* wrow = (const float4*)(rw + (size_t)h * E);
        float4 w0 = wrow[0], w1 = wrow[1];
        acc[0] += xv * w0.x; acc[1] += xv * w0.y; acc[2] += xv * w0.z; acc[3] += xv * w0.w;
        acc[4] += xv * w1.x; acc[5] += xv * w1.y; acc[6] += xv * w1.z; acc[7] += xv * w1.w;
    }
#pragma unroll
    for (int off = 16; off > 0; off >>= 1)
#pragma unroll
        for (int e = 0; e < E; e++)
            acc[e] += __shfl_down_sync(0xffffffffu, acc[e], off);

    if (lane == 0) {
        float v[E];
#pragma unroll
        for (int e = 0; e < E; e++) v[e] = acc[e] + rb[e];
        int i0 = 0;
#pragma unroll
        for (int e = 1; e < E; e++) if (v[e] > v[i0]) i0 = e;
        int i1 = -1;
#pragma unroll
        for (int e = 0; e < E; e++) {
            if (e == i0) continue;
            if (i1 < 0 || v[e] > v[i1]) i1 = e;
        }
        float e1 = expf(v[i1] - v[i0]);
        float den = 1.0f + e1;
        int p0 = atomicAdd(&g_cnt[i0], 1);
        g_tok[i0 * S + p0] = t; g_wt[i0 * S + p0] = 1.0f / den;
        int p1 = atomicAdd(&g_cnt[i1], 1);
        g_tok[i1 * S + p1] = t; g_wt[i1 * S + p1] = e1 / den;
    }
}

// ---------------------------------------------------------------------------
__global__ __launch_bounds__(256) void conv_x_kernel(const float* __restrict__ x) {
    int i = blockIdx.x * 256 + threadIdx.x;
    float4 v = ((const float4*)x)[i];
    ((__half2*)g_xh)[2 * i]     = __halves2half2(__float2half(v.x), __float2half(v.y));
    ((__half2*)g_xh)[2 * i + 1] = __halves2half2(__float2half(v.z), __float2half(v.w));
}

// ---------------------------------------------------------------------------
// gate_up weight transpose (must precede gate_up MMA): [E][H][2I] -> [E][2I][H]
// ---------------------------------------------------------------------------
__global__ __launch_bounds__(256) void transpose_gu_kernel(const float* __restrict__ in)
{
    const int R = H, C = TWO_I;
    int e = blockIdx.z;
    int r0 = blockIdx.x * 64;
    int c0 = blockIdx.y * 32;
    __shared__ float t[64][33];
    int tx = threadIdx.x & 31, ty = threadIdx.x >> 5;
    const float* ib = in + ((size_t)e * R + r0) * C + c0;
#pragma unroll
    for (int i = 0; i < 8; i++)
        t[ty + 8 * i][tx] = ib[(size_t)(ty + 8 * i) * C + tx];
    __syncthreads();
#pragma unroll
    for (int i = 0; i < 4; i++) {
        int c = ty + 8 * i;
        float a = t[2 * tx][c], b = t[2 * tx + 1][c];
        size_t o = ((size_t)e * C + c0 + c) * R + r0 + 2 * tx;
        *(__half2*)(g_guh + o) = __halves2half2(__float2half(a), __float2half(b));
    }
}

// ---------------------------------------------------------------------------
// Persistent gate_up kernel. Queue: [0, NTR) = down-weight transpose tiles,
// [NTR, NTR + 64*g_moff[E]) = gate_up MMA tiles (nt = t&63, q = t>>6).
// ---------------------------------------------------------------------------
__global__ __launch_bounds__(128, 3) void gateup_persist(
    const float* __restrict__ gub, const float* __restrict__ dwn)
{
    extern __shared__ char smem[];
    __shared__ int s_idx;
    uint32_t T0 = (s2u(smem) + 1023) & ~1023u;
    float* tbuf = (float*)smem;                     // transpose scratch (64x33)
    int tid = threadIdx.x, wid = tid >> 5, lane = tid & 31;
    int wm = (wid >> 1) * 64, wn = (wid & 1) * 32;
    int tx = tid & 31, ty4 = tid >> 5;              // for transpose items

    for (;;) {
        if (tid == 0) s_idx = atomicAdd(&g_q0, 1);
        __syncthreads();
        int idx = s_idx;

        if (idx < NTR) {
            // ---- down-weight transpose tile: [E][INTER][H] -> [E][H][INTER]
            const int R = INTER, C = H;
            int e = idx >> 10;                      // / 1024
            int rem = idx & 1023;
            int r0 = (rem & 31) * 64;
            int c0 = (rem >> 5) * 32;
            const float* ib = dwn + ((size_t)e * R + r0) * C + c0;
#pragma unroll
            for (int i = 0; i < 16; i++)
                tbuf[(ty4 + 4 * i) * 33 + tx] = ib[(size_t)(ty4 + 4 * i) * C + tx];
            __syncthreads();
#pragma unroll
            for (int i = 0; i < 8; i++) {
                int c = ty4 + 4 * i;
                float a = tbuf[(2 * tx) * 33 + c], b = tbuf[(2 * tx + 1) * 33 + c];
                size_t o = ((size_t)e * C + c0 + c) * R + r0 + 2 * tx;
                *(__half2*)(g_dwh + o) = __halves2half2(__float2half(a), __float2half(b));
            }
            __syncthreads();
            continue;
        }

        int t = idx - NTR;
        if (t >= 64 * g_moff[E]) break;
        int nt = t & 63;
        int q = t >> 6;
        int e = find_expert(q);
        int mt = q - g_moff[e];
        int cnt = g_cnt[e];
        int j0 = nt * 32;

        int seg = tid & 7;
        size_t asrc[8], bsrc[4];
        uint32_t adst[8], bdst[4];
#pragma unroll
        for (int i = 0; i < 8; i++) {
            int row = (tid >> 3) + 16 * i;
            int tr = min(mt * 128 + row, cnt - 1);
            int tok = g_tok[e * S + tr];
            asrc[i] = (size_t)tok * H + seg * 8;
            adst[i] = swz128((uint32_t)(row * 128 + seg * 16));
        }
#pragma unroll
        for (int i = 0; i < 4; i++) {
            int row = (tid >> 3) + 16 * i;
            int br = (row & 1) ? (INTER + j0 + (row >> 1)) : (j0 + (row >> 1));
            bsrc[i] = ((size_t)e * TWO_I + br) * H + seg * 8;
            bdst[i] = swz128((uint32_t)(row * 128 + seg * 16));
        }

        float acc[4][4][4];
#pragma unroll
        for (int a = 0; a < 4; a++)
#pragma unroll
            for (int b = 0; b < 4; b++)
#pragma unroll
                for (int c = 0; c < 4; c++) acc[a][b][c] = 0.0f;

        issue_chunk(T0,         0,  g_xh, g_guh, asrc, bsrc, adst, bdst);
        issue_chunk(T0 + STAGE, 64, g_xh, g_guh, asrc, bsrc, adst, bdst);
        int stage = 0;
#pragma unroll 1
        for (int c = 0; c < 16; c++) {
            if (c + 1 < 16) { CP_WAIT1(); } else { CP_WAIT0(); }
            __syncthreads();
            if (c + 2 < 16) {
                int s2 = stage + 2; if (s2 >= 3) s2 -= 3;
                issue_chunk(T0 + s2 * STAGE, (c + 2) * 64, g_xh, g_guh, asrc, bsrc, adst, bdst);
            }
            compute_chunk(T0 + stage * STAGE, wm, wn, lane, acc);
            stage = (stage + 1 == 3) ? 0 : stage + 1;
        }

        const float* gb = gub + (size_t)e * TWO_I;
#pragma unroll
        for (int mf = 0; mf < 4; mf++) {
            int r0 = wm + mf * 16 + (lane >> 2);
#pragma unroll
            for (int half = 0; half < 2; half++) {
                int mrow = mt * 128 + r0 + half * 8;
                if (mrow >= cnt) continue;
                size_t abase = ((size_t)e * S + mrow) * INTER;
#pragma unroll
                for (int nf = 0; nf < 4; nf++) {
                    int nn = wn + nf * 8 + 2 * (lane & 3);
                    int j = j0 + (nn >> 1);
                    float g = acc[mf][nf][half * 2 + 0] + gb[j];
                    float u = acc[mf][nf][half * 2 + 1] + gb[INTER + j];
                    g = fminf(g, LIMIT);
                    u = fminf(fmaxf(u, -LIMIT), LIMIT);
                    float glu = g / (1.0f + __expf(-ALPHA * g));
                    g_ah[abase + j] = __float2half((u + 1.0f) * glu);
                }
            }
        }
        __syncthreads();
    }
}

// ---------------------------------------------------------------------------
// Persistent down kernel. Queue item: nt = idx&15, q = idx>>4.
// ---------------------------------------------------------------------------
__global__ __launch_bounds__(128, 3) void down_persist(
    const float* __restrict__ dbias, float* __restrict__ out)
{
    extern __shared__ char smem[];
    __shared__ int s_idx;
    uint32_t T0 = (s2u(smem) + 1023) & ~1023u;
    int tid = threadIdx.x, wid = tid >> 5, lane = tid & 31;
    int wm = (wid >> 1) * 64, wn = (wid & 1) * 32;

    for (;;) {
        if (tid == 0) s_idx = atomicAdd(&g_q1, 1);
        __syncthreads();
        int idx = s_idx;
        if (idx >= 16 * g_moff[E]) break;
        int nt = idx & 15;
        int q = idx >> 4;
        int e = find_expert(q);
        int mt = q - g_moff[e];
        int cnt = g_cnt[e];
        int h0 = nt * 64;

        int seg = tid & 7;
        size_t asrc[8], bsrc[4];
        uint32_t adst[8], bdst[4];
#pragma unroll
        for (int i = 0; i < 8; i++) {
            int row = (tid >> 3) + 16 * i;
            int tr = min(mt * 128 + row, cnt - 1);
            asrc[i] = ((size_t)e * S + tr) * INTER + seg * 8;
            adst[i] = swz128((uint32_t)(row * 128 + seg * 16));
        }
#pragma unroll
        for (int i = 0; i < 4; i++) {
            int row = (tid >> 3) + 16 * i;
            bsrc[i] = ((size_t)e * H + h0 + row) * INTER + seg * 8;
            bdst[i] = swz128((uint32_t)(row * 128 + seg * 16));
        }

        float acc[4][4][4];
#pragma unroll
        for (int a = 0; a < 4; a++)
#pragma unroll
            for (int b = 0; b < 4; b++)
#pragma unroll
                for (int c = 0; c < 4; c++) acc[a][b][c] = 0.0f;

        issue_chunk(T0,         0,  g_ah, g_dwh, asrc, bsrc, adst, bdst);
        issue_chunk(T0 + STAGE, 64, g_ah, g_dwh, asrc, bsrc, adst, bdst);
        int stage = 0;
#pragma unroll 1
        for (int c = 0; c < 32; c++) {
            if (c + 1 < 32) { CP_WAIT1(); } else { CP_WAIT0(); }
            __syncthreads();
            if (c + 2 < 32) {
                int s2 = stage + 2; if (s2 >= 3) s2 -= 3;
                issue_chunk(T0 + s2 * STAGE, (c + 2) * 64, g_ah, g_dwh, asrc, bsrc, adst, bdst);
            }
            compute_chunk(T0 + stage * STAGE, wm, wn, lane, acc);
            stage = (stage + 1 == 3) ? 0 : stage + 1;
        }

        const float* db = dbias + (size_t)e * H;
#pragma unroll
        for (int mf = 0; mf < 4; mf++) {
            int r0 = wm + mf * 16 + (lane >> 2);
#pragma unroll
            for (int half = 0; half < 2; half++) {
                int mrow = mt * 128 + r0 + half * 8;
                if (mrow >= cnt) continue;
                int tok = g_tok[e * S + mrow];
                float w = g_wt[e * S + mrow];
                float* orow = out + (size_t)tok * H;
#pragma unroll
                for (int nf = 0; nf < 4; nf++) {
                    int h = h0 + wn + nf * 8 + 2 * (lane & 3);
                    float v0 = acc[mf][nf][half * 2 + 0] + db[h];
                    float v1 = acc[mf][nf][half * 2 + 1] + db[h + 1];
                    atomicAdd(orow + h,     w * v0);
                    atomicAdd(orow + h + 1, w * v1);
                }
            }
        }
        __syncthreads();
    }
}

// ---------------------------------------------------------------------------
extern "C" void kernel_launch(void* const* d_in, const int* in_sizes, int n_in,
                              void* d_out, int out_size) {
    const float* x     = (const float*)d_in[0];
    const float* rw    = (const float*)d_in[1];
    const float* rb    = (const float*)d_in[2];
    const float* gup   = (const float*)d_in[3];
    const float* gub   = (const float*)d_in[4];
    const float* dwn   = (const float*)d_in[5];
    const float* dbias = (const float*)d_in[6];
    float* out = (float*)d_out;

    cudaFuncSetAttribute(gateup_persist, cudaFuncAttributeMaxDynamicSharedMemorySize, SMEM_REQ);
    cudaFuncSetAttribute(down_persist,   cudaFuncAttributeMaxDynamicSharedMemorySize, SMEM_REQ);

    cudaMemsetAsync(out, 0, (size_t)out_size * sizeof(float));
    init_kernel<<<1, 32>>>();
    router_kernel<<<S / 8, 256>>>(x, rw, rb);
    prefix_kernel<<<1, 32>>>();
    conv_x_kernel<<<(S * H / 4) / 256, 256>>>(x);

    {   // gate_up weights: [E][1024][4096] -> [E][4096][1024] fp16
        dim3 g(H / 64, TWO_I / 32, E);
        transpose_gu_kernel<<<g, 256>>>(gup);
    }
    // persistent gate_up (also transposes down weights off the same queue)
    gateup_persist<<<NPERS, 128, SMEM_REQ>>>(gub, dwn);
    // persistent down
    down_persist<<<NPERS, 128, SMEM_REQ>>>(dbias, out);
}

// round 13
// speedup vs baseline: 1.1160x; 1.1160x over previous
#include <cuda_runtime.h>
#include <cuda_fp16.h>
#include <cstdint>

#define S 2048
#define H 1024
#define E 8
#define INTER 2048
#define TWO_I 4096
#define ALPHA 1.702f
#define LIMIT 7.0f

// ---------------- device scratch (device-code references ONLY) ----------------
__device__ int   g_cnt[E];
__device__ int   g_tok[E * S];
__device__ float g_wt[E * S];
__device__ __align__(128) __half g_xh[S * H];
__device__ __align__(128) __half g_guh[(size_t)E * TWO_I * H];
__device__ __align__(128) __half g_dwh[(size_t)E * H * INTER];
__device__ __align__(128) __half g_ah[(size_t)E * S * INTER];

// ---------------- helpers ----------------
__device__ __forceinline__ uint32_t s2u(const void* p) {
    uint32_t a;
    asm("{ .reg .u64 t; cvta.to.shared.u64 t, %1; cvt.u32.u64 %0, t; }" : "=r"(a) : "l"(p));
    return a;
}
__device__ __forceinline__ uint32_t swz128(uint32_t o) { return o ^ ((o >> 3) & 0x70); }

#define CP16(dst, src) \
    asm volatile("cp.async.cg.shared.global [%0], [%1], 16;" :: "r"(dst), "l"(src) : "memory")
#define CP_COMMIT() asm volatile("cp.async.commit_group;" ::: "memory")
#define CP_WAIT0()  asm volatile("cp.async.wait_group 0;" ::: "memory")
#define CP_WAIT1()  asm volatile("cp.async.wait_group 1;" ::: "memory")

__device__ __forceinline__ void ldsm4(uint32_t addr, uint32_t* r) {
    asm volatile("ldmatrix.sync.aligned.m8n8.x4.shared.b16 {%0,%1,%2,%3}, [%4];"
                 : "=r"(r[0]), "=r"(r[1]), "=r"(r[2]), "=r"(r[3]) : "r"(addr));
}
__device__ __forceinline__ void mma16816(float* d, const uint32_t* a, uint32_t b0, uint32_t b1) {
    asm volatile(
        "mma.sync.aligned.m16n8k16.row.col.f32.f16.f16.f32 "
        "{%0,%1,%2,%3}, {%4,%5,%6,%7}, {%8,%9}, {%0,%1,%2,%3};"
        : "+f"(d[0]), "+f"(d[1]), "+f"(d[2]), "+f"(d[3])
        : "r"(a[0]), "r"(a[1]), "r"(a[2]), "r"(a[3]), "r"(b0), "r"(b1));
}

// Stage: Ah 16K | Bh 8K = 24KB
#define BOFF_H 16384
#define STAGE  24576
#define SMEM_GU   (1024 + 3 * STAGE)   // gate_up: 3 stages, occ 3
#define SMEM_DOWN (1024 + 2 * STAGE)   // down:    2 stages, occ 4 (single wave)

// one K=64 chunk; block tile 128x64, warp tile 64x32 (4 warps), single fp16 term
__device__ __forceinline__ void compute_chunk(uint32_t base, int wm, int wn, int lane,
                                              float acc[4][4][4])
{
    uint32_t sA = base, sB = base + BOFF_H;
    int arow = wm + (lane & 15);
    int brow = wn + (lane & 15);
    uint32_t klane = (uint32_t)((lane >> 4) << 4);
#pragma unroll
    for (int ks = 0; ks < 4; ks++) {
        uint32_t ko = (uint32_t)(ks * 32) + klane;
        uint32_t ah[4][4];
#pragma unroll
        for (int mf = 0; mf < 4; mf++) {
            uint32_t off = swz128((uint32_t)((arow + mf * 16) * 128) + ko);
            ldsm4(sA + off, ah[mf]);
        }
#pragma unroll
        for (int nh = 0; nh < 2; nh++) {
            uint32_t boff = swz128((uint32_t)((brow + nh * 16) * 128) + ko);
            uint32_t bh[4];
            ldsm4(sB + boff, bh);
#pragma unroll
            for (int mf = 0; mf < 4; mf++) {
                mma16816(acc[mf][2 * nh],     ah[mf], bh[0], bh[2]);
                mma16816(acc[mf][2 * nh + 1], ah[mf], bh[1], bh[3]);
            }
        }
    }
}

// 128 threads: A rows 0..127 (8 CP16), B rows 0..63 (4 CP16)
__device__ __forceinline__ void issue_chunk(
    uint32_t base, int k0,
    const __half* Ah, const __half* Bh,
    const size_t* asrc, const size_t* bsrc,
    const uint32_t* adst, const uint32_t* bdst)
{
#pragma unroll
    for (int i = 0; i < 8; i++)
        CP16(base + adst[i], (const char*)(Ah + asrc[i] + k0));
#pragma unroll
    for (int i = 0; i < 4; i++)
        CP16(base + BOFF_H + bdst[i], (const char*)(Bh + bsrc[i] + k0));
    CP_COMMIT();
}

// ---------------------------------------------------------------------------
__global__ void init_kernel() {
    if (threadIdx.x < E) g_cnt[threadIdx.x] = 0;
}

// ---------------------------------------------------------------------------
// Router + x->fp16 conversion fused: one warp per token, shuffle reduce.
// ---------------------------------------------------------------------------
__global__ __launch_bounds__(256) void router_kernel(
    const float* __restrict__ x, const float* __restrict__ rw, const float* __restrict__ rb)
{
    int warp = threadIdx.x >> 5, lane = threadIdx.x & 31;
    int t = blockIdx.x * 8 + warp;
    const float* xr = x + (size_t)t * H;
    __half* xo = g_xh + (size_t)t * H;

    float acc[E];
#pragma unroll
    for (int e = 0; e < E; e++) acc[e] = 0.0f;
#pragma unroll 4
    for (int i = 0; i < 32; i++) {
        int h = i * 32 + lane;
        float xv = xr[h];
        xo[h] = __float2half(xv);                      // fused conversion
        const float4* wrow = (const float4*)(rw + (size_t)h * E);
        float4 w0 = wrow[0], w1 = wrow[1];
        acc[0] += xv * w0.x; acc[1] += xv * w0.y; acc[2] += xv * w0.z; acc[3] += xv * w0.w;
        acc[4] += xv * w1.x; acc[5] += xv * w1.y; acc[6] += xv * w1.z; acc[7] += xv * w1.w;
    }
#pragma unroll
    for (int off = 16; off > 0; off >>= 1)
#pragma unroll
        for (int e = 0; e < E; e++)
            acc[e] += __shfl_down_sync(0xffffffffu, acc[e], off);

    if (lane == 0) {
        float v[E];
#pragma unroll
        for (int e = 0; e < E; e++) v[e] = acc[e] + rb[e];
        int i0 = 0;
#pragma unroll
        for (int e = 1; e < E; e++) if (v[e] > v[i0]) i0 = e;
        int i1 = -1;
#pragma unroll
        for (int e = 0; e < E; e++) {
            if (e == i0) continue;
            if (i1 < 0 || v[e] > v[i1]) i1 = e;
        }
        float e1 = expf(v[i1] - v[i0]);
        float den = 1.0f + e1;
        int p0 = atomicAdd(&g_cnt[i0], 1);
        g_tok[i0 * S + p0] = t; g_wt[i0 * S + p0] = 1.0f / den;
        int p1 = atomicAdd(&g_cnt[i1], 1);
        g_tok[i1 * S + p1] = t; g_wt[i1 * S + p1] = e1 / den;
    }
}

// ---------------------------------------------------------------------------
// weight transpose to fp16, outputs bound in DEVICE code.
// in [E][R][C] fp32 -> out [E][C][R] fp16. Tile 64(R) x 32(C).
// ---------------------------------------------------------------------------
template <int WHICH>   // 0 = gate_up (R=H, C=2I), 1 = down (R=INTER, C=H)
__global__ __launch_bounds__(256) void transpose_half_kernel(const float* __restrict__ in)
{
    const int R = (WHICH == 0) ? H : INTER;
    const int C = (WHICH == 0) ? TWO_I : H;
    __half* ohi = (WHICH == 0) ? g_guh : g_dwh;

    int e = blockIdx.z;
    int r0 = blockIdx.x * 64;
    int c0 = blockIdx.y * 32;
    __shared__ float t[64][33];
    int tx = threadIdx.x & 31, ty = threadIdx.x >> 5;
    const float* ib = in + ((size_t)e * R + r0) * C + c0;
#pragma unroll
    for (int i = 0; i < 8; i++)
        t[ty + 8 * i][tx] = ib[(size_t)(ty + 8 * i) * C + tx];
    __syncthreads();
#pragma unroll
    for (int i = 0; i < 4; i++) {
        int c = ty + 8 * i;
        float a = t[2 * tx][c], b = t[2 * tx + 1][c];
        size_t o = ((size_t)e * C + c0 + c) * R + r0 + 2 * tx;
        *(__half2*)(ohi + o) = __halves2half2(__float2half(a), __float2half(b));
    }
}

// ---------------------------------------------------------------------------
// gate_up: CTA = (expert, 128-token M-tile, 32-j N-tile = 64 interleaved cols).
// 128 threads, 4 warps of 64x32. K = H = 1024, 16 chunks of 64.
// 3-stage cp.async pipeline, occ 3.
// ---------------------------------------------------------------------------
__global__ __launch_bounds__(128, 3) void gateup_mma_kernel(const float* __restrict__ gub) {
    int e = blockIdx.z, mt = blockIdx.x, nt = blockIdx.y;
    int cnt = g_cnt[e];
    if (mt * 128 >= cnt) return;

    extern __shared__ char smem[];
    uint32_t T0 = (s2u(smem) + 1023) & ~1023u;
    int tid = threadIdx.x, wid = tid >> 5, lane = tid & 31;
    int wm = (wid >> 1) * 64, wn = (wid & 1) * 32;
    int j0 = nt * 32;

    int seg = tid & 7;
    size_t asrc[8], bsrc[4];
    uint32_t adst[8], bdst[4];
#pragma unroll
    for (int i = 0; i < 8; i++) {
        int row = (tid >> 3) + 16 * i;                 // 0..127
        int tr = min(mt * 128 + row, cnt - 1);
        int tok = g_tok[e * S + tr];
        asrc[i] = (size_t)tok * H + seg * 8;
        adst[i] = swz128((uint32_t)(row * 128 + seg * 16));
    }
#pragma unroll
    for (int i = 0; i < 4; i++) {
        int row = (tid >> 3) + 16 * i;                 // 0..63
        int br = (row & 1) ? (INTER + j0 + (row >> 1)) : (j0 + (row >> 1));
        bsrc[i] = ((size_t)e * TWO_I + br) * H + seg * 8;
        bdst[i] = swz128((uint32_t)(row * 128 + seg * 16));
    }

    float acc[4][4][4];
#pragma unroll
    for (int a = 0; a < 4; a++)
#pragma unroll
        for (int b = 0; b < 4; b++)
#pragma unroll
            for (int c = 0; c < 4; c++) acc[a][b][c] = 0.0f;

    issue_chunk(T0,         0,  g_xh, g_guh, asrc, bsrc, adst, bdst);
    issue_chunk(T0 + STAGE, 64, g_xh, g_guh, asrc, bsrc, adst, bdst);
    int stage = 0;
#pragma unroll 1
    for (int c = 0; c < 16; c++) {
        if (c + 1 < 16) { CP_WAIT1(); } else { CP_WAIT0(); }
        __syncthreads();
        if (c + 2 < 16) {
            int s2 = stage + 2; if (s2 >= 3) s2 -= 3;
            issue_chunk(T0 + s2 * STAGE, (c + 2) * 64, g_xh, g_guh, asrc, bsrc, adst, bdst);
        }
        compute_chunk(T0 + stage * STAGE, wm, wn, lane, acc);
        stage = (stage + 1 == 3) ? 0 : stage + 1;
    }

    const float* gb = gub + (size_t)e * TWO_I;
#pragma unroll
    for (int mf = 0; mf < 4; mf++) {
        int r0 = wm + mf * 16 + (lane >> 2);
#pragma unroll
        for (int half = 0; half < 2; half++) {
            int mrow = mt * 128 + r0 + half * 8;
            if (mrow >= cnt) continue;
            size_t abase = ((size_t)e * S + mrow) * INTER;
#pragma unroll
            for (int nf = 0; nf < 4; nf++) {
                int nn = wn + nf * 8 + 2 * (lane & 3);
                int j = j0 + (nn >> 1);
                float g = acc[mf][nf][half * 2 + 0] + gb[j];
                float u = acc[mf][nf][half * 2 + 1] + gb[INTER + j];
                g = fminf(g, LIMIT);
                u = fminf(fmaxf(u, -LIMIT), LIMIT);
                float glu = g / (1.0f + __expf(-ALPHA * g));
                g_ah[abase + j] = __float2half((u + 1.0f) * glu);
            }
        }
    }
}

// ---------------------------------------------------------------------------
// down: CTA = (expert, 128-row M-tile, 64-h N-tile). 128 threads, 4 warps.
// K = INTER = 2048, 32 chunks of 64. 2-stage pipeline, occ 4 -> single wave.
// ---------------------------------------------------------------------------
__global__ __launch_bounds__(128, 4) void down_mma_kernel(
    const float* __restrict__ dbias, float* __restrict__ out)
{
    int e = blockIdx.z, mt = blockIdx.x, nt = blockIdx.y;
    int cnt = g_cnt[e];
    if (mt * 128 >= cnt) return;

    extern __shared__ char smem[];
    uint32_t T0 = (s2u(smem) + 1023) & ~1023u;
    int tid = threadIdx.x, wid = tid >> 5, lane = tid & 31;
    int wm = (wid >> 1) * 64, wn = (wid & 1) * 32;
    int h0 = nt * 64;

    int seg = tid & 7;
    size_t asrc[8], bsrc[4];
    uint32_t adst[8], bdst[4];
#pragma unroll
    for (int i = 0; i < 8; i++) {
        int row = (tid >> 3) + 16 * i;
        int tr = min(mt * 128 + row, cnt - 1);
        asrc[i] = ((size_t)e * S + tr) * INTER + seg * 8;
        adst[i] = swz128((uint32_t)(row * 128 + seg * 16));
    }
#pragma unroll
    for (int i = 0; i < 4; i++) {
        int row = (tid >> 3) + 16 * i;                 // 0..63
        bsrc[i] = ((size_t)e * H + h0 + row) * INTER + seg * 8;
        bdst[i] = swz128((uint32_t)(row * 128 + seg * 16));
    }

    float acc[4][4][4];
#pragma unroll
    for (int a = 0; a < 4; a++)
#pragma unroll
        for (int b = 0; b < 4; b++)
#pragma unroll
            for (int c = 0; c < 4; c++) acc[a][b][c] = 0.0f;

    issue_chunk(T0, 0, g_ah, g_dwh, asrc, bsrc, adst, bdst);
#pragma unroll 1
    for (int c = 0; c < 32; c++) {
        if (c + 1 < 32)
            issue_chunk(T0 + ((c + 1) & 1) * STAGE, (c + 1) * 64,
                        g_ah, g_dwh, asrc, bsrc, adst, bdst);
        if (c + 1 < 32) { CP_WAIT1(); } else { CP_WAIT0(); }
        __syncthreads();
        compute_chunk(T0 + (c & 1) * STAGE, wm, wn, lane, acc);
        __syncthreads();
    }

    const float* db = dbias + (size_t)e * H;
#pragma unroll
    for (int mf = 0; mf < 4; mf++) {
        int r0 = wm + mf * 16 + (lane >> 2);
#pragma unroll
        for (int half = 0; half < 2; half++) {
            int mrow = mt * 128 + r0 + half * 8;
            if (mrow >= cnt) continue;
            int tok = g_tok[e * S + mrow];
            float w = g_wt[e * S + mrow];
            float* orow = out + (size_t)tok * H;
#pragma unroll
            for (int nf = 0; nf < 4; nf++) {
                int h = h0 + wn + nf * 8 + 2 * (lane & 3);
                float v0 = acc[mf][nf][half * 2 + 0] + db[h];
                float v1 = acc[mf][nf][half * 2 + 1] + db[h + 1];
                atomicAdd(orow + h,     w * v0);
                atomicAdd(orow + h + 1, w * v1);
            }
        }
    }
}

// ---------------------------------------------------------------------------
extern "C" void kernel_launch(void* const* d_in, const int* in_sizes, int n_in,
                              void* d_out, int out_size) {
    const float* x     = (const float*)d_in[0];
    const float* rw    = (const float*)d_in[1];
    const float* rb    = (const float*)d_in[2];
    const float* gup   = (const float*)d_in[3];
    const float* gub   = (const float*)d_in[4];
    const float* dwn   = (const float*)d_in[5];
    const float* dbias = (const float*)d_in[6];
    float* out = (float*)d_out;

    cudaFuncSetAttribute(gateup_mma_kernel, cudaFuncAttributeMaxDynamicSharedMemorySize, SMEM_GU);
    cudaFuncSetAttribute(down_mma_kernel,   cudaFuncAttributeMaxDynamicSharedMemorySize, SMEM_DOWN);

    cudaMemsetAsync(out, 0, (size_t)out_size * sizeof(float));
    init_kernel<<<1, 32>>>();
    router_kernel<<<S / 8, 256>>>(x, rw, rb);   // also writes g_xh

    {   // gate_up weights: [E][1024][4096] -> [E][4096][1024] fp16
        dim3 g(H / 64, TWO_I / 32, E);
        transpose_half_kernel<0><<<g, 256>>>(gup);
    }
    {   // down weights: [E][2048][1024] -> [E][1024][2048] fp16
        dim3 g(INTER / 64, H / 32, E);
        transpose_half_kernel<1><<<g, 256>>>(dwn);
    }
    {
        dim3 g(S / 128, INTER / 32, E);   // (16, 64, 8), early-exit past bucket count
        gateup_mma_kernel<<<g, 128, SMEM_GU>>>(gub);
    }
    {
        dim3 g(S / 128, H / 64, E);       // (16, 16, 8)
        down_mma_kernel<<<g, 128, SMEM_DOWN>>>(dbias, out);
    }
}

// round 14
// speedup vs baseline: 1.1318x; 1.0141x over previous
#include <cuda_runtime.h>
#include <cuda_fp16.h>
#include <cstdint>

#define S 2048
#define H 1024
#define E 8
#define INTER 2048
#define TWO_I 4096
#define ALPHA 1.702f
#define LIMIT 7.0f

// ---------------- device scratch (device-code references ONLY) ----------------
__device__ int   g_cnt[E];
__device__ int   g_tok[E * S];
__device__ float g_wt[E * S];
__device__ __align__(128) __half g_xh[S * H];
__device__ __align__(128) __half g_guh[(size_t)E * TWO_I * H];
__device__ __align__(128) __half g_dwh[(size_t)E * H * INTER];
__device__ __align__(128) __half g_ah[(size_t)E * S * INTER];

// ---------------- helpers ----------------
__device__ __forceinline__ uint32_t s2u(const void* p) {
    uint32_t a;
    asm("{ .reg .u64 t; cvta.to.shared.u64 t, %1; cvt.u32.u64 %0, t; }" : "=r"(a) : "l"(p));
    return a;
}
__device__ __forceinline__ uint32_t swz128(uint32_t o) { return o ^ ((o >> 3) & 0x70); }

#define CP16(dst, src) \
    asm volatile("cp.async.cg.shared.global [%0], [%1], 16;" :: "r"(dst), "l"(src) : "memory")
#define CP_COMMIT() asm volatile("cp.async.commit_group;" ::: "memory")
#define CP_WAIT0()  asm volatile("cp.async.wait_group 0;" ::: "memory")
#define CP_WAIT1()  asm volatile("cp.async.wait_group 1;" ::: "memory")

__device__ __forceinline__ void ldsm4(uint32_t addr, uint32_t* r) {
    asm volatile("ldmatrix.sync.aligned.m8n8.x4.shared.b16 {%0,%1,%2,%3}, [%4];"
                 : "=r"(r[0]), "=r"(r[1]), "=r"(r[2]), "=r"(r[3]) : "r"(addr));
}
__device__ __forceinline__ void mma16816(float* d, const uint32_t* a, uint32_t b0, uint32_t b1) {
    asm volatile(
        "mma.sync.aligned.m16n8k16.row.col.f32.f16.f16.f32 "
        "{%0,%1,%2,%3}, {%4,%5,%6,%7}, {%8,%9}, {%0,%1,%2,%3};"
        : "+f"(d[0]), "+f"(d[1]), "+f"(d[2]), "+f"(d[3])
        : "r"(a[0]), "r"(a[1]), "r"(a[2]), "r"(a[3]), "r"(b0), "r"(b1));
}

// Stage: Ah 16K | Bh 8K = 24KB
#define BOFF_H 16384
#define STAGE  24576
#define SMEM_GU   (1024 + 3 * STAGE)   // gate_up: 3 stages, occ 3
#define SMEM_DOWN (1024 + 2 * STAGE)   // down:    2 stages, occ 4

// one K=64 chunk; block tile 128x64, warp tile 64x32 (4 warps), single fp16 term
__device__ __forceinline__ void compute_chunk(uint32_t base, int wm, int wn, int lane,
                                              float acc[4][4][4])
{
    uint32_t sA = base, sB = base + BOFF_H;
    int arow = wm + (lane & 15);
    int brow = wn + (lane & 15);
    uint32_t klane = (uint32_t)((lane >> 4) << 4);
#pragma unroll
    for (int ks = 0; ks < 4; ks++) {
        uint32_t ko = (uint32_t)(ks * 32) + klane;
        uint32_t ah[4][4];
#pragma unroll
        for (int mf = 0; mf < 4; mf++) {
            uint32_t off = swz128((uint32_t)((arow + mf * 16) * 128) + ko);
            ldsm4(sA + off, ah[mf]);
        }
#pragma unroll
        for (int nh = 0; nh < 2; nh++) {
            uint32_t boff = swz128((uint32_t)((brow + nh * 16) * 128) + ko);
            uint32_t bh[4];
            ldsm4(sB + boff, bh);
#pragma unroll
            for (int mf = 0; mf < 4; mf++) {
                mma16816(acc[mf][2 * nh],     ah[mf], bh[0], bh[2]);
                mma16816(acc[mf][2 * nh + 1], ah[mf], bh[1], bh[3]);
            }
        }
    }
}

__device__ __forceinline__ void issue_chunk(
    uint32_t base, int k0,
    const __half* Ah, const __half* Bh,
    const size_t* asrc, const size_t* bsrc,
    const uint32_t* adst, const uint32_t* bdst)
{
#pragma unroll
    for (int i = 0; i < 8; i++)
        CP16(base + adst[i], (const char*)(Ah + asrc[i] + k0));
#pragma unroll
    for (int i = 0; i < 4; i++)
        CP16(base + BOFF_H + bdst[i], (const char*)(Bh + bsrc[i] + k0));
    CP_COMMIT();
}

// ---------------------------------------------------------------------------
__global__ void init_kernel() {
    if (threadIdx.x < E) g_cnt[threadIdx.x] = 0;
}

// ---------------------------------------------------------------------------
// Router + x->fp16 conversion fused: one warp per token, shuffle reduce.
// ---------------------------------------------------------------------------
__global__ __launch_bounds__(256) void router_kernel(
    const float* __restrict__ x, const float* __restrict__ rw, const float* __restrict__ rb)
{
    int warp = threadIdx.x >> 5, lane = threadIdx.x & 31;
    int t = blockIdx.x * 8 + warp;
    const float* xr = x + (size_t)t * H;
    __half* xo = g_xh + (size_t)t * H;

    float acc[E];
#pragma unroll
    for (int e = 0; e < E; e++) acc[e] = 0.0f;
#pragma unroll 4
    for (int i = 0; i < 32; i++) {
        int h = i * 32 + lane;
        float xv = xr[h];
        xo[h] = __float2half(xv);
        const float4* wrow = (const float4*)(rw + (size_t)h * E);
        float4 w0 = wrow[0], w1 = wrow[1];
        acc[0] += xv * w0.x; acc[1] += xv * w0.y; acc[2] += xv * w0.z; acc[3] += xv * w0.w;
        acc[4] += xv * w1.x; acc[5] += xv * w1.y; acc[6] += xv * w1.z; acc[7] += xv * w1.w;
    }
#pragma unroll
    for (int off = 16; off > 0; off >>= 1)
#pragma unroll
        for (int e = 0; e < E; e++)
            acc[e] += __shfl_down_sync(0xffffffffu, acc[e], off);

    if (lane == 0) {
        float v[E];
#pragma unroll
        for (int e = 0; e < E; e++) v[e] = acc[e] + rb[e];
        int i0 = 0;
#pragma unroll
        for (int e = 1; e < E; e++) if (v[e] > v[i0]) i0 = e;
        int i1 = -1;
#pragma unroll
        for (int e = 0; e < E; e++) {
            if (e == i0) continue;
            if (i1 < 0 || v[e] > v[i1]) i1 = e;
        }
        float e1 = expf(v[i1] - v[i0]);
        float den = 1.0f + e1;
        int p0 = atomicAdd(&g_cnt[i0], 1);
        g_tok[i0 * S + p0] = t; g_wt[i0 * S + p0] = 1.0f / den;
        int p1 = atomicAdd(&g_cnt[i1], 1);
        g_tok[i1 * S + p1] = t; g_wt[i1 * S + p1] = e1 / den;
    }
}

// ---------------------------------------------------------------------------
// weight transpose to fp16, outputs bound in DEVICE code.
// in [E][R][C] fp32 -> out [E][C][R] fp16. Tile 64(R) x 32(C).
// ---------------------------------------------------------------------------
template <int WHICH>   // 0 = gate_up (R=H, C=2I), 1 = down (R=INTER, C=H)
__global__ __launch_bounds__(256) void transpose_half_kernel(const float* __restrict__ in)
{
    const int R = (WHICH == 0) ? H : INTER;
    const int C = (WHICH == 0) ? TWO_I : H;
    __half* ohi = (WHICH == 0) ? g_guh : g_dwh;

    int e = blockIdx.z;
    int r0 = blockIdx.x * 64;
    int c0 = blockIdx.y * 32;
    __shared__ float t[64][33];
    int tx = threadIdx.x & 31, ty = threadIdx.x >> 5;
    const float* ib = in + ((size_t)e * R + r0) * C + c0;
#pragma unroll
    for (int i = 0; i < 8; i++)
        t[ty + 8 * i][tx] = ib[(size_t)(ty + 8 * i) * C + tx];
    __syncthreads();
#pragma unroll
    for (int i = 0; i < 4; i++) {
        int c = ty + 8 * i;
        float a = t[2 * tx][c], b = t[2 * tx + 1][c];
        size_t o = ((size_t)e * C + c0 + c) * R + r0 + 2 * tx;
        *(__half2*)(ohi + o) = __halves2half2(__float2half(a), __float2half(b));
    }
}

// ---------------------------------------------------------------------------
// gate_up: CTA = (expert, 128-token M-tile, 32-j N-tile = 64 interleaved cols).
// 128 threads, 4 warps of 64x32. K = H = 1024, 16 chunks of 64. 3-stage pipeline.
// ---------------------------------------------------------------------------
__global__ __launch_bounds__(128, 3) void gateup_mma_kernel(const float* __restrict__ gub) {
    int e = blockIdx.z, mt = blockIdx.x, nt = blockIdx.y;
    int cnt = g_cnt[e];
    if (mt * 128 >= cnt) return;

    extern __shared__ char smem[];
    uint32_t T0 = (s2u(smem) + 1023) & ~1023u;
    int tid = threadIdx.x, wid = tid >> 5, lane = tid & 31;
    int wm = (wid >> 1) * 64, wn = (wid & 1) * 32;
    int j0 = nt * 32;

    int seg = tid & 7;
    size_t asrc[8], bsrc[4];
    uint32_t adst[8], bdst[4];
#pragma unroll
    for (int i = 0; i < 8; i++) {
        int row = (tid >> 3) + 16 * i;                 // 0..127
        int tr = min(mt * 128 + row, cnt - 1);
        int tok = g_tok[e * S + tr];
        asrc[i] = (size_t)tok * H + seg * 8;
        adst[i] = swz128((uint32_t)(row * 128 + seg * 16));
    }
#pragma unroll
    for (int i = 0; i < 4; i++) {
        int row = (tid >> 3) + 16 * i;                 // 0..63
        int br = (row & 1) ? (INTER + j0 + (row >> 1)) : (j0 + (row >> 1));
        bsrc[i] = ((size_t)e * TWO_I + br) * H + seg * 8;
        bdst[i] = swz128((uint32_t)(row * 128 + seg * 16));
    }

    float acc[4][4][4];
#pragma unroll
    for (int a = 0; a < 4; a++)
#pragma unroll
        for (int b = 0; b < 4; b++)
#pragma unroll
            for (int c = 0; c < 4; c++) acc[a][b][c] = 0.0f;

    issue_chunk(T0,         0,  g_xh, g_guh, asrc, bsrc, adst, bdst);
    issue_chunk(T0 + STAGE, 64, g_xh, g_guh, asrc, bsrc, adst, bdst);
    int stage = 0;
#pragma unroll 1
    for (int c = 0; c < 16; c++) {
        if (c + 1 < 16) { CP_WAIT1(); } else { CP_WAIT0(); }
        __syncthreads();
        if (c + 2 < 16) {
            int s2 = stage + 2; if (s2 >= 3) s2 -= 3;
            issue_chunk(T0 + s2 * STAGE, (c + 2) * 64, g_xh, g_guh, asrc, bsrc, adst, bdst);
        }
        compute_chunk(T0 + stage * STAGE, wm, wn, lane, acc);
        stage = (stage + 1 == 3) ? 0 : stage + 1;
    }

    const float* gb = gub + (size_t)e * TWO_I;
#pragma unroll
    for (int mf = 0; mf < 4; mf++) {
        int r0 = wm + mf * 16 + (lane >> 2);
#pragma unroll
        for (int half = 0; half < 2; half++) {
            int mrow = mt * 128 + r0 + half * 8;
            if (mrow >= cnt) continue;
            size_t abase = ((size_t)e * S + mrow) * INTER;
#pragma unroll
            for (int nf = 0; nf < 4; nf++) {
                int nn = wn + nf * 8 + 2 * (lane & 3);
                int j = j0 + (nn >> 1);
                float g = acc[mf][nf][half * 2 + 0] + gb[j];
                float u = acc[mf][nf][half * 2 + 1] + gb[INTER + j];
                g = fminf(g, LIMIT);
                u = fminf(fmaxf(u, -LIMIT), LIMIT);
                float glu = g / (1.0f + __expf(-ALPHA * g));
                g_ah[abase + j] = __float2half((u + 1.0f) * glu);
            }
        }
    }
}

// ---------------------------------------------------------------------------
// down: CTA = (expert, 128-row M-tile, 64-h N-tile). 128 threads, 4 warps.
// K = INTER = 2048, 32 chunks of 64. 2-stage pipeline, occ 4.
// ---------------------------------------------------------------------------
__global__ __launch_bounds__(128, 4) void down_mma_kernel(
    const float* __restrict__ dbias, float* __restrict__ out)
{
    int e = blockIdx.z, mt = blockIdx.x, nt = blockIdx.y;
    int cnt = g_cnt[e];
    if (mt * 128 >= cnt) return;

    extern __shared__ char smem[];
    uint32_t T0 = (s2u(smem) + 1023) & ~1023u;
    int tid = threadIdx.x, wid = tid >> 5, lane = tid & 31;
    int wm = (wid >> 1) * 64, wn = (wid & 1) * 32;
    int h0 = nt * 64;

    int seg = tid & 7;
    size_t asrc[8], bsrc[4];
    uint32_t adst[8], bdst[4];
#pragma unroll
    for (int i = 0; i < 8; i++) {
        int row = (tid >> 3) + 16 * i;
        int tr = min(mt * 128 + row, cnt - 1);
        asrc[i] = ((size_t)e * S + tr) * INTER + seg * 8;
        adst[i] = swz128((uint32_t)(row * 128 + seg * 16));
    }
#pragma unroll
    for (int i = 0; i < 4; i++) {
        int row = (tid >> 3) + 16 * i;                 // 0..63
        bsrc[i] = ((size_t)e * H + h0 + row) * INTER + seg * 8;
        bdst[i] = swz128((uint32_t)(row * 128 + seg * 16));
    }

    float acc[4][4][4];
#pragma unroll
    for (int a = 0; a < 4; a++)
#pragma unroll
        for (int b = 0; b < 4; b++)
#pragma unroll
            for (int c = 0; c < 4; c++) acc[a][b][c] = 0.0f;

    issue_chunk(T0, 0, g_ah, g_dwh, asrc, bsrc, adst, bdst);
#pragma unroll 1
    for (int c = 0; c < 32; c++) {
        if (c + 1 < 32)
            issue_chunk(T0 + ((c + 1) & 1) * STAGE, (c + 1) * 64,
                        g_ah, g_dwh, asrc, bsrc, adst, bdst);
        if (c + 1 < 32) { CP_WAIT1(); } else { CP_WAIT0(); }
        __syncthreads();
        compute_chunk(T0 + (c & 1) * STAGE, wm, wn, lane, acc);
        __syncthreads();
    }

    const float* db = dbias + (size_t)e * H;
#pragma unroll
    for (int mf = 0; mf < 4; mf++) {
        int r0 = wm + mf * 16 + (lane >> 2);
#pragma unroll
        for (int half = 0; half < 2; half++) {
            int mrow = mt * 128 + r0 + half * 8;
            if (mrow >= cnt) continue;
            int tok = g_tok[e * S + mrow];
            float w = g_wt[e * S + mrow];
            float* orow = out + (size_t)tok * H;
#pragma unroll
            for (int nf = 0; nf < 4; nf++) {
                int h = h0 + wn + nf * 8 + 2 * (lane & 3);
                float v0 = acc[mf][nf][half * 2 + 0] + db[h];
                float v1 = acc[mf][nf][half * 2 + 1] + db[h + 1];
                atomicAdd(orow + h,     w * v0);
                atomicAdd(orow + h + 1, w * v1);
            }
        }
    }
}

// ---------------------------------------------------------------------------
extern "C" void kernel_launch(void* const* d_in, const int* in_sizes, int n_in,
                              void* d_out, int out_size) {
    const float* x     = (const float*)d_in[0];
    const float* rw    = (const float*)d_in[1];
    const float* rb    = (const float*)d_in[2];
    const float* gup   = (const float*)d_in[3];
    const float* gub   = (const float*)d_in[4];
    const float* dwn   = (const float*)d_in[5];
    const float* dbias = (const float*)d_in[6];
    float* out = (float*)d_out;

    // host-side stream/event objects, created once (first call is uncaptured)
    static cudaStream_t sGu = nullptr, sDw = nullptr;
    static cudaEvent_t evFork = nullptr, evGu = nullptr, evDw = nullptr;
    static bool attrs_set = false;
    if (!sGu) {
        cudaStreamCreateWithFlags(&sGu, cudaStreamNonBlocking);
        cudaStreamCreateWithFlags(&sDw, cudaStreamNonBlocking);
        cudaEventCreateWithFlags(&evFork, cudaEventDisableTiming);
        cudaEventCreateWithFlags(&evGu,   cudaEventDisableTiming);
        cudaEventCreateWithFlags(&evDw,   cudaEventDisableTiming);
    }
    if (!attrs_set) {
        cudaFuncSetAttribute(gateup_mma_kernel, cudaFuncAttributeMaxDynamicSharedMemorySize, SMEM_GU);
        cudaFuncSetAttribute(down_mma_kernel,   cudaFuncAttributeMaxDynamicSharedMemorySize, SMEM_DOWN);
        attrs_set = true;
    }

    cudaMemsetAsync(out, 0, (size_t)out_size * sizeof(float));
    init_kernel<<<1, 32>>>();

    // fork: both weight transposes run on side streams, concurrent with router
    cudaEventRecord(evFork, 0);
    cudaStreamWaitEvent(sGu, evFork, 0);
    cudaStreamWaitEvent(sDw, evFork, 0);
    {
        dim3 g(H / 64, TWO_I / 32, E);
        transpose_half_kernel<0><<<g, 256, 0, sGu>>>(gup);
        cudaEventRecord(evGu, sGu);
    }
    {
        dim3 g(INTER / 64, H / 32, E);
        transpose_half_kernel<1><<<g, 256, 0, sDw>>>(dwn);
        cudaEventRecord(evDw, sDw);
    }

    router_kernel<<<S / 8, 256>>>(x, rw, rb);   // main stream; also writes g_xh

    // gate_up needs router (in-stream) + gu transpose
    cudaStreamWaitEvent(0, evGu, 0);
    {
        dim3 g(S / 128, INTER / 32, E);
        gateup_mma_kernel<<<g, 128, SMEM_GU>>>(gub);
    }
    // down needs gate_up (in-stream) + dw transpose (hidden under gate_up)
    cudaStreamWaitEvent(0, evDw, 0);
    {
        dim3 g(S / 128, H / 64, E);
        down_mma_kernel<<<g, 128, SMEM_DOWN>>>(dbias, out);
    }
}

// round 15
// speedup vs baseline: 1.1395x; 1.0068x over previous
#include <cuda_runtime.h>
#include <cuda_fp16.h>
#include <cstdint>

#define S 2048
#define H 1024
#define E 8
#define INTER 2048
#define TWO_I 4096
#define ALPHA 1.702f
#define LIMIT 7.0f

// ---------------- device scratch (device-code references ONLY) ----------------
__device__ int   g_cnt[E];
__device__ int   g_tok[E * S];
__device__ float g_wt[E * S];
__device__ __align__(128) __half g_xh[S * H];
__device__ __align__(128) __half g_guh[(size_t)E * TWO_I * H];
__device__ __align__(128) __half g_dwh[(size_t)E * H * INTER];
__device__ __align__(128) __half g_ah[(size_t)E * S * INTER];

// ---------------- helpers ----------------
__device__ __forceinline__ uint32_t s2u(const void* p) {
    uint32_t a;
    asm("{ .reg .u64 t; cvta.to.shared.u64 t, %1; cvt.u32.u64 %0, t; }" : "=r"(a) : "l"(p));
    return a;
}
__device__ __forceinline__ uint32_t swz128(uint32_t o) { return o ^ ((o >> 3) & 0x70); }

#define CP16(dst, src) \
    asm volatile("cp.async.cg.shared.global [%0], [%1], 16;" :: "r"(dst), "l"(src) : "memory")
#define CP_COMMIT() asm volatile("cp.async.commit_group;" ::: "memory")
#define CP_WAIT0()  asm volatile("cp.async.wait_group 0;" ::: "memory")
#define CP_WAIT1()  asm volatile("cp.async.wait_group 1;" ::: "memory")

__device__ __forceinline__ void ldsm4(uint32_t addr, uint32_t* r) {
    asm volatile("ldmatrix.sync.aligned.m8n8.x4.shared.b16 {%0,%1,%2,%3}, [%4];"
                 : "=r"(r[0]), "=r"(r[1]), "=r"(r[2]), "=r"(r[3]) : "r"(addr));
}
__device__ __forceinline__ void mma16816(float* d, const uint32_t* a, uint32_t b0, uint32_t b1) {
    asm volatile(
        "mma.sync.aligned.m16n8k16.row.col.f32.f16.f16.f32 "
        "{%0,%1,%2,%3}, {%4,%5,%6,%7}, {%8,%9}, {%0,%1,%2,%3};"
        : "+f"(d[0]), "+f"(d[1]), "+f"(d[2]), "+f"(d[3])
        : "r"(a[0]), "r"(a[1]), "r"(a[2]), "r"(a[3]), "r"(b0), "r"(b1));
}

// Stage: Ah 16K | Bh 8K = 24KB
#define BOFF_H 16384
#define STAGE  24576
#define SMEM_GU   (1024 + 3 * STAGE)   // gate_up: 3 stages, occ 3
#define SMEM_DOWN (1024 + 2 * STAGE)   // down:    2 stages, occ 4

// one K=64 chunk; block tile 128x64, warp tile 64x32 (4 warps), single fp16 term
__device__ __forceinline__ void compute_chunk(uint32_t base, int wm, int wn, int lane,
                                              float acc[4][4][4])
{
    uint32_t sA = base, sB = base + BOFF_H;
    int arow = wm + (lane & 15);
    int brow = wn + (lane & 15);
    uint32_t klane = (uint32_t)((lane >> 4) << 4);
#pragma unroll
    for (int ks = 0; ks < 4; ks++) {
        uint32_t ko = (uint32_t)(ks * 32) + klane;
        uint32_t ah[4][4];
#pragma unroll
        for (int mf = 0; mf < 4; mf++) {
            uint32_t off = swz128((uint32_t)((arow + mf * 16) * 128) + ko);
            ldsm4(sA + off, ah[mf]);
        }
#pragma unroll
        for (int nh = 0; nh < 2; nh++) {
            uint32_t boff = swz128((uint32_t)((brow + nh * 16) * 128) + ko);
            uint32_t bh[4];
            ldsm4(sB + boff, bh);
#pragma unroll
            for (int mf = 0; mf < 4; mf++) {
                mma16816(acc[mf][2 * nh],     ah[mf], bh[0], bh[2]);
                mma16816(acc[mf][2 * nh + 1], ah[mf], bh[1], bh[3]);
            }
        }
    }
}

__device__ __forceinline__ void issue_chunk(
    uint32_t base, int k0,
    const __half* Ah, const __half* Bh,
    const size_t* asrc, const size_t* bsrc,
    const uint32_t* adst, const uint32_t* bdst)
{
#pragma unroll
    for (int i = 0; i < 8; i++)
        CP16(base + adst[i], (const char*)(Ah + asrc[i] + k0));
#pragma unroll
    for (int i = 0; i < 4; i++)
        CP16(base + BOFF_H + bdst[i], (const char*)(Bh + bsrc[i] + k0));
    CP_COMMIT();
}

// ---------------------------------------------------------------------------
__global__ void init_kernel() {
    if (threadIdx.x < E) g_cnt[threadIdx.x] = 0;
}

// ---------------------------------------------------------------------------
// Router + x->fp16 fused: ONE BLOCK (128 thr) PER TOKEN, thread owns 8 h.
// ---------------------------------------------------------------------------
__global__ __launch_bounds__(128) void router_kernel(
    const float* __restrict__ x, const float* __restrict__ rw, const float* __restrict__ rb)
{
    int t = blockIdx.x;
    int tid = threadIdx.x, lane = tid & 31, warp = tid >> 5;
    const float4* xr = (const float4*)(x + (size_t)t * H);
    __half2* xo = (__half2*)(g_xh + (size_t)t * H);

    float acc[E];
#pragma unroll
    for (int e = 0; e < E; e++) acc[e] = 0.0f;
#pragma unroll
    for (int q = 0; q < 2; q++) {
        int idx = tid + q * 128;              // float4 index, coalesced
        float4 v = xr[idx];
        xo[2 * idx]     = __halves2half2(__float2half(v.x), __float2half(v.y));
        xo[2 * idx + 1] = __halves2half2(__float2half(v.z), __float2half(v.w));
        int hbase = idx * 4;
        float xv[4] = {v.x, v.y, v.z, v.w};
#pragma unroll
        for (int j = 0; j < 4; j++) {
            const float4* wrow = (const float4*)(rw + (size_t)(hbase + j) * E);
            float4 w0 = wrow[0], w1 = wrow[1];
            acc[0] += xv[j] * w0.x; acc[1] += xv[j] * w0.y;
            acc[2] += xv[j] * w0.z; acc[3] += xv[j] * w0.w;
            acc[4] += xv[j] * w1.x; acc[5] += xv[j] * w1.y;
            acc[6] += xv[j] * w1.z; acc[7] += xv[j] * w1.w;
        }
    }
#pragma unroll
    for (int off = 16; off > 0; off >>= 1)
#pragma unroll
        for (int e = 0; e < E; e++)
            acc[e] += __shfl_down_sync(0xffffffffu, acc[e], off);

    __shared__ float sm[4][E];
    if (lane == 0) {
#pragma unroll
        for (int e = 0; e < E; e++) sm[warp][e] = acc[e];
    }
    __syncthreads();
    if (tid == 0) {
        float v[E];
#pragma unroll
        for (int e = 0; e < E; e++)
            v[e] = sm[0][e] + sm[1][e] + sm[2][e] + sm[3][e] + rb[e];
        int i0 = 0;
#pragma unroll
        for (int e = 1; e < E; e++) if (v[e] > v[i0]) i0 = e;
        int i1 = -1;
#pragma unroll
        for (int e = 0; e < E; e++) {
            if (e == i0) continue;
            if (i1 < 0 || v[e] > v[i1]) i1 = e;
        }
        float e1 = expf(v[i1] - v[i0]);
        float den = 1.0f + e1;
        int p0 = atomicAdd(&g_cnt[i0], 1);
        g_tok[i0 * S + p0] = t; g_wt[i0 * S + p0] = 1.0f / den;
        int p1 = atomicAdd(&g_cnt[i1], 1);
        g_tok[i1 * S + p1] = t; g_wt[i1 * S + p1] = e1 / den;
    }
}

// ---------------------------------------------------------------------------
// weight transpose to fp16, outputs bound in DEVICE code.
// in [E][R][C] fp32 -> out [E][C][R] fp16. Tile 64(R) x 32(C).
// ---------------------------------------------------------------------------
template <int WHICH>   // 0 = gate_up (R=H, C=2I), 1 = down (R=INTER, C=H)
__global__ __launch_bounds__(256) void transpose_half_kernel(const float* __restrict__ in)
{
    const int R = (WHICH == 0) ? H : INTER;
    const int C = (WHICH == 0) ? TWO_I : H;
    __half* ohi = (WHICH == 0) ? g_guh : g_dwh;

    int e = blockIdx.z;
    int r0 = blockIdx.x * 64;
    int c0 = blockIdx.y * 32;
    __shared__ float t[64][33];
    int tx = threadIdx.x & 31, ty = threadIdx.x >> 5;
    const float* ib = in + ((size_t)e * R + r0) * C + c0;
#pragma unroll
    for (int i = 0; i < 8; i++)
        t[ty + 8 * i][tx] = ib[(size_t)(ty + 8 * i) * C + tx];
    __syncthreads();
#pragma unroll
    for (int i = 0; i < 4; i++) {
        int c = ty + 8 * i;
        float a = t[2 * tx][c], b = t[2 * tx + 1][c];
        size_t o = ((size_t)e * C + c0 + c) * R + r0 + 2 * tx;
        *(__half2*)(ohi + o) = __halves2half2(__float2half(a), __float2half(b));
    }
}

// ---------------------------------------------------------------------------
// gate_up: CTA = (expert, 128-token M-tile, 32-j N-tile = 64 interleaved cols).
// 128 threads, 4 warps of 64x32. K = H = 1024, 16 chunks of 64. 3-stage pipeline.
// ---------------------------------------------------------------------------
__global__ __launch_bounds__(128, 3) void gateup_mma_kernel(const float* __restrict__ gub) {
    int e = blockIdx.z, mt = blockIdx.x, nt = blockIdx.y;
    int cnt = g_cnt[e];
    if (mt * 128 >= cnt) return;

    extern __shared__ char smem[];
    uint32_t T0 = (s2u(smem) + 1023) & ~1023u;
    int tid = threadIdx.x, wid = tid >> 5, lane = tid & 31;
    int wm = (wid >> 1) * 64, wn = (wid & 1) * 32;
    int j0 = nt * 32;

    int seg = tid & 7;
    size_t asrc[8], bsrc[4];
    uint32_t adst[8], bdst[4];
#pragma unroll
    for (int i = 0; i < 8; i++) {
        int row = (tid >> 3) + 16 * i;                 // 0..127
        int tr = min(mt * 128 + row, cnt - 1);
        int tok = g_tok[e * S + tr];
        asrc[i] = (size_t)tok * H + seg * 8;
        adst[i] = swz128((uint32_t)(row * 128 + seg * 16));
    }
#pragma unroll
    for (int i = 0; i < 4; i++) {
        int row = (tid >> 3) + 16 * i;                 // 0..63
        int br = (row & 1) ? (INTER + j0 + (row >> 1)) : (j0 + (row >> 1));
        bsrc[i] = ((size_t)e * TWO_I + br) * H + seg * 8;
        bdst[i] = swz128((uint32_t)(row * 128 + seg * 16));
    }

    float acc[4][4][4];
#pragma unroll
    for (int a = 0; a < 4; a++)
#pragma unroll
        for (int b = 0; b < 4; b++)
#pragma unroll
            for (int c = 0; c < 4; c++) acc[a][b][c] = 0.0f;

    issue_chunk(T0,         0,  g_xh, g_guh, asrc, bsrc, adst, bdst);
    issue_chunk(T0 + STAGE, 64, g_xh, g_guh, asrc, bsrc, adst, bdst);
    int stage = 0;
#pragma unroll 1
    for (int c = 0; c < 16; c++) {
        if (c + 1 < 16) { CP_WAIT1(); } else { CP_WAIT0(); }
        __syncthreads();
        if (c + 2 < 16) {
            int s2 = stage + 2; if (s2 >= 3) s2 -= 3;
            issue_chunk(T0 + s2 * STAGE, (c + 2) * 64, g_xh, g_guh, asrc, bsrc, adst, bdst);
        }
        compute_chunk(T0 + stage * STAGE, wm, wn, lane, acc);
        stage = (stage + 1 == 3) ? 0 : stage + 1;
    }

    const float* gb = gub + (size_t)e * TWO_I;
#pragma unroll
    for (int mf = 0; mf < 4; mf++) {
        int r0 = wm + mf * 16 + (lane >> 2);
#pragma unroll
        for (int half = 0; half < 2; half++) {
            int mrow = mt * 128 + r0 + half * 8;
            if (mrow >= cnt) continue;
            size_t abase = ((size_t)e * S + mrow) * INTER;
#pragma unroll
            for (int nf = 0; nf < 4; nf++) {
                int nn = wn + nf * 8 + 2 * (lane & 3);
                int j = j0 + (nn >> 1);
                float g = acc[mf][nf][half * 2 + 0] + gb[j];
                float u = acc[mf][nf][half * 2 + 1] + gb[INTER + j];
                g = fminf(g, LIMIT);
                u = fminf(fmaxf(u, -LIMIT), LIMIT);
                float glu = g / (1.0f + __expf(-ALPHA * g));
                g_ah[abase + j] = __float2half((u + 1.0f) * glu);
            }
        }
    }
}

// ---------------------------------------------------------------------------
// down: CTA = (expert, 128-row M-tile, 64-h N-tile). 128 threads, 4 warps.
// K = INTER = 2048, 32 chunks of 64. 2-stage pipeline, occ 4.
// ---------------------------------------------------------------------------
__global__ __launch_bounds__(128, 4) void down_mma_kernel(
    const float* __restrict__ dbias, float* __restrict__ out)
{
    int e = blockIdx.z, mt = blockIdx.x, nt = blockIdx.y;
    int cnt = g_cnt[e];
    if (mt * 128 >= cnt) return;

    extern __shared__ char smem[];
    uint32_t T0 = (s2u(smem) + 1023) & ~1023u;
    int tid = threadIdx.x, wid = tid >> 5, lane = tid & 31;
    int wm = (wid >> 1) * 64, wn = (wid & 1) * 32;
    int h0 = nt * 64;

    int seg = tid & 7;
    size_t asrc[8], bsrc[4];
    uint32_t adst[8], bdst[4];
#pragma unroll
    for (int i = 0; i < 8; i++) {
        int row = (tid >> 3) + 16 * i;
        int tr = min(mt * 128 + row, cnt - 1);
        asrc[i] = ((size_t)e * S + tr) * INTER + seg * 8;
        adst[i] = swz128((uint32_t)(row * 128 + seg * 16));
    }
#pragma unroll
    for (int i = 0; i < 4; i++) {
        int row = (tid >> 3) + 16 * i;                 // 0..63
        bsrc[i] = ((size_t)e * H + h0 + row) * INTER + seg * 8;
        bdst[i] = swz128((uint32_t)(row * 128 + seg * 16));
    }

    float acc[4][4][4];
#pragma unroll
    for (int a = 0; a < 4; a++)
#pragma unroll
        for (int b = 0; b < 4; b++)
#pragma unroll
            for (int c = 0; c < 4; c++) acc[a][b][c] = 0.0f;

    issue_chunk(T0, 0, g_ah, g_dwh, asrc, bsrc, adst, bdst);
#pragma unroll 1
    for (int c = 0; c < 32; c++) {
        if (c + 1 < 32)
            issue_chunk(T0 + ((c + 1) & 1) * STAGE, (c + 1) * 64,
                        g_ah, g_dwh, asrc, bsrc, adst, bdst);
        if (c + 1 < 32) { CP_WAIT1(); } else { CP_WAIT0(); }
        __syncthreads();
        compute_chunk(T0 + (c & 1) * STAGE, wm, wn, lane, acc);
        __syncthreads();
    }

    const float* db = dbias + (size_t)e * H;
#pragma unroll
    for (int mf = 0; mf < 4; mf++) {
        int r0 = wm + mf * 16 + (lane >> 2);
#pragma unroll
        for (int half = 0; half < 2; half++) {
            int mrow = mt * 128 + r0 + half * 8;
            if (mrow >= cnt) continue;
            int tok = g_tok[e * S + mrow];
            float w = g_wt[e * S + mrow];
            float* orow = out + (size_t)tok * H;
#pragma unroll
            for (int nf = 0; nf < 4; nf++) {
                int h = h0 + wn + nf * 8 + 2 * (lane & 3);
                float v0 = acc[mf][nf][half * 2 + 0] + db[h];
                float v1 = acc[mf][nf][half * 2 + 1] + db[h + 1];
                atomicAdd(orow + h,     w * v0);
                atomicAdd(orow + h + 1, w * v1);
            }
        }
    }
}

// ---------------------------------------------------------------------------
extern "C" void kernel_launch(void* const* d_in, const int* in_sizes, int n_in,
                              void* d_out, int out_size) {
    const float* x     = (const float*)d_in[0];
    const float* rw    = (const float*)d_in[1];
    const float* rb    = (const float*)d_in[2];
    const float* gup   = (const float*)d_in[3];
    const float* gub   = (const float*)d_in[4];
    const float* dwn   = (const float*)d_in[5];
    const float* dbias = (const float*)d_in[6];
    float* out = (float*)d_out;

    static cudaStream_t sGu = nullptr, sDw = nullptr;
    static cudaEvent_t evFork = nullptr, evGu = nullptr, evDw = nullptr;
    static bool attrs_set = false;
    if (!sGu) {
        cudaStreamCreateWithFlags(&sGu, cudaStreamNonBlocking);
        cudaStreamCreateWithFlags(&sDw, cudaStreamNonBlocking);
        cudaEventCreateWithFlags(&evFork, cudaEventDisableTiming);
        cudaEventCreateWithFlags(&evGu,   cudaEventDisableTiming);
        cudaEventCreateWithFlags(&evDw,   cudaEventDisableTiming);
    }
    if (!attrs_set) {
        cudaFuncSetAttribute(gateup_mma_kernel, cudaFuncAttributeMaxDynamicSharedMemorySize, SMEM_GU);
        cudaFuncSetAttribute(down_mma_kernel,   cudaFuncAttributeMaxDynamicSharedMemorySize, SMEM_DOWN);
        attrs_set = true;
    }

    init_kernel<<<1, 32>>>();
    cudaEventRecord(evFork, 0);

    // sGu: gate_up weight transpose, concurrent with router
    cudaStreamWaitEvent(sGu, evFork, 0);
    {
        dim3 g(H / 64, TWO_I / 32, E);
        transpose_half_kernel<0><<<g, 256, 0, sGu>>>(gup);
        cudaEventRecord(evGu, sGu);
    }
    // sDw: out-memset now; down-weight transpose AFTER tr_gu (hides under gateup)
    cudaStreamWaitEvent(sDw, evFork, 0);
    cudaMemsetAsync(out, 0, (size_t)out_size * sizeof(float), sDw);
    cudaStreamWaitEvent(sDw, evGu, 0);
    {
        dim3 g(INTER / 64, H / 32, E);
        transpose_half_kernel<1><<<g, 256, 0, sDw>>>(dwn);
        cudaEventRecord(evDw, sDw);
    }

    router_kernel<<<S, 128>>>(x, rw, rb);   // main stream; also writes g_xh

    cudaStreamWaitEvent(0, evGu, 0);
    {
        dim3 g(S / 128, INTER / 32, E);
        gateup_mma_kernel<<<g, 128, SMEM_GU>>>(gub);
    }
    cudaStreamWaitEvent(0, evDw, 0);
    {
        dim3 g(S / 128, H / 64, E);
        down_mma_kernel<<<g, 128, SMEM_DOWN>>>(dbias, out);
    }
}